// round 12
// baseline (speedup 1.0000x reference)
#include <cuda_runtime.h>
#include <cuda_bf16.h>
#include <cstdint>

// ---------------------------------------------------------------------------
// Sparse 3x3x3 conv chain, N=1e6 voxels. R12 = R11 +
//  * PITCH 12 for CIN=8 kernels (was 8 -> 2-way LDS bank conflict every load)
//  * ILP=3 on K1/K5
//  * fold_wd0 merged into pack_all; build_compact wider
// ---------------------------------------------------------------------------

#define MAXN 1000000
#define NSM  148
#define LOV  20

__device__ int      g_mtype;
__device__ int      g_l8[(size_t)MAXN * 8];    // entries 0..7 (e0 carries cnt)
__device__ int      g_lov[(size_t)MAXN * LOV]; // entries 8.. (rare)
__device__ unsigned g_xbf[(size_t)MAXN * 4];   // x as bf16x2, 8 ch
__device__ unsigned g_t32p[(size_t)MAXN * 16]; // bf16x2, 32 ch
__device__ unsigned g_t8ap[(size_t)MAXN * 4];
__device__ unsigned g_t8bp[(size_t)MAXN * 4];
__device__ unsigned g_wpack[10368 + 4320 + 2592 + 2592 + 10368 + 17280];

#define WQ0 0                  // K1 <8,32>  pitch 12 : 10368
#define WQ1 (WQ0 + 10368)      // K2 <32,8>  pitch 20 :  4320
#define WQ2 (WQ1 + 4320)       // K3 <8,8>   pitch 12 :  2592
#define WQ3 (WQ2 + 2592)       // K4 <8,8>
#define WQ4 (WQ3 + 2592)       // K5 <8,32>
#define WQ5 (WQ4 + 10368)      // K6 <32,32> pitch 20 : 17280

// ---------------------------------------------------------------------------
__global__ void detect_mask(const unsigned int* __restrict__ m) {
    __shared__ int s_u8, s_f32;
    if (threadIdx.x == 0) { s_u8 = 0; s_f32 = 0; }
    __syncthreads();
    int loc_u8 = 0, loc_f32 = 0;
    for (int i = threadIdx.x; i < 65536; i += blockDim.x) {
        unsigned v = m[i];
        if (v == 0x3F800000u) loc_f32 = 1;
        else if (v > 1u)      loc_u8 = 1;
    }
    if (loc_u8)  atomicOr(&s_u8, 1);
    if (loc_f32) atomicOr(&s_f32, 1);
    __syncthreads();
    if (threadIdx.x == 0) g_mtype = s_f32 ? 2 : (s_u8 ? 1 : 0);
}

__global__ void build_compact(const int* __restrict__ nbr,
                              const void* __restrict__ maskv, int N) {
    int n = blockIdx.x * blockDim.x + threadIdx.x;
    if (n >= N) return;
    const int mt = g_mtype;
    const int*           mi = (const int*)maskv;
    const unsigned char* mb = (const unsigned char*)maskv;
    const float*         mf = (const float*)maskv;
    int cnt = 0, first = 0;
    int* lst = &g_l8[(size_t)n * 8];
#pragma unroll 1
    for (int k = 0; k < 27; k++) {
        if (k == 13) continue;
        size_t o = (size_t)k * N + n;
        bool on;
        if (mt == 0)      on = mi[o] != 0;
        else if (mt == 1) on = mb[o] != 0;
        else              on = mf[o] != 0.0f;
        if (on) {
            int e = (k << 20) | nbr[o];
            if (cnt == 0)      first = e;
            else if (cnt < 8)  lst[cnt] = e;
            else               g_lov[(size_t)n * LOV + cnt - 8] = e;
            cnt++;
        }
    }
    lst[0] = first | (cnt << 27);
    if (cnt < 2) lst[1] = 0;
    if (cnt < 3) lst[2] = 0;
    if (cnt < 4) lst[3] = 0;
}

__device__ __forceinline__ unsigned f2b2(float lo, float hi) {
    __nv_bfloat162 p = __floats2bfloat162_rn(lo, hi);
    return *reinterpret_cast<unsigned*>(&p);
}
__device__ __forceinline__ float2 bf2f(unsigned u) {
    float2 r;
    r.x = __uint_as_float(u << 16);
    r.y = __uint_as_float(u & 0xFFFF0000u);
    return r;
}
__device__ __forceinline__ __nv_bfloat162 u2b(unsigned u) {
    return *reinterpret_cast<__nv_bfloat162*>(&u);
}

// Pack one bf16x2 word of W[k][c][oc] -> rows [k][oc][c/2], pitch PITCH.
// FOLD4: sum 4 row-blocks of CIN=32 source (tile fold for Wd0).
template <bool FOLD4>
__device__ __forceinline__ void pack_one(const float* W, unsigned* dst,
                                         int CIN, int COUT, int PITCH, int i) {
    int c2n = CIN >> 1;
    int c2 = i % c2n;
    int rest = i / c2n;
    int oc = rest % COUT, k = rest / COUT;
    float a, b;
    if constexpr (FOLD4) {
        // W is Wd0 [27][32][32]; fold: sum_t W[k][c+8t][oc]
        a = 0.f; b = 0.f;
#pragma unroll
        for (int t = 0; t < 4; t++) {
            a += W[(k * 32 + 2 * c2     + 8 * t) * 32 + oc];
            b += W[(k * 32 + 2 * c2 + 1 + 8 * t) * 32 + oc];
        }
    } else {
        a = W[(k * CIN + 2 * c2) * COUT + oc];
        b = W[(k * CIN + 2 * c2 + 1) * COUT + oc];
    }
    dst[(k * COUT + oc) * PITCH + c2] = f2b2(a, b);
}
__global__ void pack_all(const float* __restrict__ Wd0,
                         const float* __restrict__ Wd1,
                         const float* __restrict__ Wd2,
                         const float* __restrict__ Wu0,
                         const float* __restrict__ Wu1,
                         const float* __restrict__ Wu2,
                         unsigned* __restrict__ wp) {
    int i = blockIdx.x * blockDim.x + threadIdx.x;
    const int s0 = 3456, s1 = 3456, s2 = 864, s3 = 864, s4 = 3456, s5 = 13824;
    if (i < s0) { pack_one<true >(Wd0, wp + WQ0,  8, 32, 12, i); return; }
    i -= s0;
    if (i < s1) { pack_one<false>(Wd1, wp + WQ1, 32,  8, 20, i); return; }
    i -= s1;
    if (i < s2) { pack_one<false>(Wd2, wp + WQ2,  8,  8, 12, i); return; }
    i -= s2;
    if (i < s3) { pack_one<false>(Wu0, wp + WQ3,  8,  8, 12, i); return; }
    i -= s3;
    if (i < s4) { pack_one<false>(Wu1, wp + WQ4,  8, 32, 12, i); return; }
    i -= s4;
    if (i < s5) { pack_one<false>(Wu2, wp + WQ5, 32, 32, 20, i); return; }
}

// Pack x [N*8 fp32] -> bf16x2 [N*4]
__global__ void pack_x(const float* __restrict__ x, unsigned* __restrict__ dst,
                       int n4) {
    int i = blockIdx.x * blockDim.x + threadIdx.x;
    if (i >= n4) return;
    float2 v = reinterpret_cast<const float2*>(x)[i];
    dst[i] = f2b2(v.x, v.y);
}

// ---------------------------------------------------------------------------
// Warp-per-voxel (x ILP) sparse conv, packed bf16 HFMA2 inner product.
// EPI: 0 none; 1: out = xres(bf16) - conv (8ch); 2: out = tile(xres fp32)
//      + conv (32ch).
// ---------------------------------------------------------------------------
template <int CIN, int COUT, int EPI, int TB, int MINB, int ILP, bool OUTBF>
__global__ void __launch_bounds__(TB, MINB)
conv_kernel(const unsigned* __restrict__ in,     // bf16x2, CIN/2 words/voxel
            const unsigned* __restrict__ WP,
            const void* __restrict__ xres,
            void* __restrict__ out, int N) {
    constexpr int csn   = (COUT == 32) ? CIN : (CIN / 4);
    constexpr int PITCH = (CIN == 8) ? 12 : 20;
    extern __shared__ unsigned Ws[];  // [27][COUT][PITCH]

    const int tid = threadIdx.x;
    for (int i = tid; i < 27 * COUT * PITCH; i += blockDim.x)
        Ws[i] = WP[i];
    __syncthreads();

    const int lane = tid & 31;
    const int warp = tid >> 5;
    const int wpb  = blockDim.x >> 5;

    int oc, cs0;
    if (COUT == 32) { oc = lane; cs0 = 0; }
    else            { oc = lane & 7; cs0 = (lane >> 3) * csn; }

    const int gw      = blockIdx.x * wpb + warp;
    const int gstride = gridDim.x * wpb;

    for (int base = gw * ILP; base < N; base += gstride * ILP) {
        int4 L[ILP];
#pragma unroll
        for (int j = 0; j < ILP; j++) {
            int n = base + j;
            L[j] = (n < N)
                 ? *reinterpret_cast<const int4*>(&g_l8[(size_t)n * 8])
                 : make_int4(0, 0, 0, 0);
        }
#pragma unroll
        for (int j = 0; j < ILP; j++) {
            const int n = base + j;
            if (n >= N) break;
            const int cnt = ((unsigned)L[j].x) >> 27;

            __nv_bfloat162 z = __float2bfloat162_rn(0.f);
            __nv_bfloat162 b0 = z, b1 = z, b2 = z, b3 = z;

            auto do_entry = [&](int e) {
                const int k   = (e >> 20) & 31;
                const int src = e & 0xFFFFF;
                const unsigned* gp = in + (size_t)src * (CIN / 2) + (cs0 >> 1);
                const unsigned* wrow =
                    &Ws[(k * COUT + oc) * PITCH + (cs0 >> 1)];
                if constexpr (csn == 2) {
                    b0 = __hfma2(u2b(gp[0]), u2b(wrow[0]), b0);
                } else {
#pragma unroll
                    for (int b = 0; b < csn / 8; b++) {
                        uint4 gv = reinterpret_cast<const uint4*>(gp)[b];
                        uint4 wv = reinterpret_cast<const uint4*>(wrow)[b];
                        b0 = __hfma2(u2b(gv.x), u2b(wv.x), b0);
                        b1 = __hfma2(u2b(gv.y), u2b(wv.y), b1);
                        b2 = __hfma2(u2b(gv.z), u2b(wv.z), b2);
                        b3 = __hfma2(u2b(gv.w), u2b(wv.w), b3);
                    }
                }
            };

            do_entry((13 << 20) | n);                 // center tap
            if (cnt > 0) do_entry(L[j].x & 0x07FFFFFF);
            if (cnt > 1) do_entry(L[j].y);
            if (cnt > 2) do_entry(L[j].z);
            if (cnt > 3) do_entry(L[j].w);
            if (cnt > 4) {
                int4 M = *reinterpret_cast<const int4*>(&g_l8[(size_t)n * 8 + 4]);
                do_entry(M.x);
                if (cnt > 5) do_entry(M.y);
                if (cnt > 6) do_entry(M.z);
                if (cnt > 7) do_entry(M.w);
#pragma unroll 1
                for (int i = 8; i < cnt; i++)
                    do_entry(g_lov[(size_t)n * LOV + i - 8]);
            }

            float2 f0 = bf2f(*reinterpret_cast<unsigned*>(&b0));
            float2 f1 = bf2f(*reinterpret_cast<unsigned*>(&b1));
            float2 f2 = bf2f(*reinterpret_cast<unsigned*>(&b2));
            float2 f3 = bf2f(*reinterpret_cast<unsigned*>(&b3));
            float acc = ((f0.x + f0.y) + (f1.x + f1.y))
                      + ((f2.x + f2.y) + (f3.x + f3.y));

            if constexpr (COUT == 8) {
                acc += __shfl_xor_sync(0xffffffffu, acc, 8);
                acc += __shfl_xor_sync(0xffffffffu, acc, 16);
                float v = acc;
                if constexpr (EPI == 1) {
                    unsigned xp = ((const unsigned*)xres)
                                      [(size_t)n * 4 + ((lane & 7) >> 1)];
                    float2 xv = bf2f(xp);
                    v = ((lane & 1) ? xv.y : xv.x) - v;
                }
                if constexpr (OUTBF) {
                    float pv = __shfl_xor_sync(0xffffffffu, v, 1);
                    if (lane < 8 && (lane & 1) == 0)
                        ((unsigned*)out)[(size_t)n * 4 + (lane >> 1)] = f2b2(v, pv);
                } else {
                    if (lane < 8)
                        ((float*)out)[(size_t)n * 8 + lane] = v;
                }
            } else {
                float v = acc;
                if constexpr (EPI == 2)
                    v += ((const float*)xres)[(size_t)n * 8 + (lane & 7)];
                if constexpr (OUTBF) {
                    float pv = __shfl_xor_sync(0xffffffffu, v, 1);
                    if ((lane & 1) == 0)
                        ((unsigned*)out)[(size_t)n * 16 + (lane >> 1)] = f2b2(v, pv);
                } else {
                    ((float*)out)[(size_t)n * 32 + lane] = v;
                }
            }
        }
    }
}

// ---------------------------------------------------------------------------
extern "C" void kernel_launch(void* const* d_in, const int* in_sizes, int n_in,
                              void* d_out, int out_size) {
    const float* x    = (const float*)d_in[0];
    const int*   nbr  = (const int*)d_in[1];
    const void*  mask = (const void*)d_in[2];
    const float* Wd0  = (const float*)d_in[3];
    const float* Wd1  = (const float*)d_in[4];
    const float* Wd2  = (const float*)d_in[5];
    const float* Wu0  = (const float*)d_in[6];
    const float* Wu1  = (const float*)d_in[7];
    const float* Wu2  = (const float*)d_in[8];
    float*       out  = (float*)d_out;
    const int N = in_sizes[0] / 8;

    unsigned *xbf, *t32, *t8a, *t8b, *wp;
    cudaGetSymbolAddress((void**)&xbf, g_xbf);
    cudaGetSymbolAddress((void**)&t32, g_t32p);
    cudaGetSymbolAddress((void**)&t8a, g_t8ap);
    cudaGetSymbolAddress((void**)&t8b, g_t8bp);
    cudaGetSymbolAddress((void**)&wp,  g_wpack);

    const int sm_8_32  = 10368 * 4;   // 41,472 B
    const int sm_32_8  = 4320  * 4;
    const int sm_8_8   = 2592  * 4;
    const int sm_32_32 = 17280 * 4;   // 69,120 B

    cudaFuncSetAttribute(
        (const void*)conv_kernel<32, 32, 2, 512, 2, 2, false>,
        cudaFuncAttributeMaxDynamicSharedMemorySize, sm_32_32);
    cudaFuncSetAttribute(
        (const void*)conv_kernel<8, 32, 0, 256, 6, 3, true>,
        cudaFuncAttributeMaxDynamicSharedMemorySize, sm_8_32);

    detect_mask<<<1, 1024>>>((const unsigned int*)mask);
    build_compact<<<(N + 511) / 512, 512>>>(nbr, mask, N);
    pack_x<<<(N * 4 + 255) / 256, 256>>>(x, xbf, N * 4);
    pack_all<<<(3456 * 3 + 864 * 2 + 13824 + 255) / 256, 256>>>(
        Wd0, Wd1, Wd2, Wu0, Wu1, Wu2, wp);

    // K1: 8 -> 32 (tile folded into packed weights)
    conv_kernel<8, 32, 0, 256, 6, 3, true>
        <<<NSM * 6, 256, sm_8_32>>>(xbf, wp + WQ0, x, t32, N);
    // K2: 32 -> 8
    conv_kernel<32, 8, 0, 256, 6, 2, true>
        <<<NSM * 6, 256, sm_32_8>>>(t32, wp + WQ1, x, t8a, N);
    // K3: 8 -> 8, epilogue r = x(bf16) - d
    conv_kernel<8, 8, 1, 256, 6, 4, true>
        <<<NSM * 6, 256, sm_8_8>>>(t8a, wp + WQ2, xbf, t8b, N);
    // K4: 8 -> 8
    conv_kernel<8, 8, 0, 256, 6, 4, true>
        <<<NSM * 6, 256, sm_8_8>>>(t8b, wp + WQ3, x, t8a, N);
    // K5: 8 -> 32
    conv_kernel<8, 32, 0, 256, 6, 3, true>
        <<<NSM * 6, 256, sm_8_32>>>(t8a, wp + WQ4, x, t32, N);
    // K6: 32 -> 32, epilogue out = tile(x fp32) + conv
    conv_kernel<32, 32, 2, 512, 2, 2, false>
        <<<NSM * 2, 512, sm_32_32>>>(t32, wp + WQ5, x, out, N);
}

// round 13
// speedup vs baseline: 1.1534x; 1.1534x over previous
#include <cuda_runtime.h>
#include <cuda_bf16.h>
#include <cstdint>

// ---------------------------------------------------------------------------
// Sparse 3x3x3 conv chain, N=1e6 voxels. R13 = R11 launch configs +
// conflict-free weight LDS at zero smem cost:
//  * K1/K5 (<8,32>): pitch 8 with chunk swizzle (+ (oc&4) words)
//  * K3/K4 (<8,8>):  pitch 12 (scalar-LDS bank fix, smem still tiny)
//  * K2/K6 (pitch 20): already conflict-free
// ---------------------------------------------------------------------------

#define MAXN 1000000
#define NSM  148
#define LOV  20

__device__ int      g_mtype;
__device__ int      g_l8[(size_t)MAXN * 8];    // entries 0..7 (e0 carries cnt)
__device__ int      g_lov[(size_t)MAXN * LOV]; // entries 8.. (rare)
__device__ unsigned g_xbf[(size_t)MAXN * 4];   // x as bf16x2, 8 ch
__device__ unsigned g_t32p[(size_t)MAXN * 16]; // bf16x2, 32 ch
__device__ unsigned g_t8ap[(size_t)MAXN * 4];
__device__ unsigned g_t8bp[(size_t)MAXN * 4];
__device__ unsigned g_wpack[6912 + 4320 + 2592 + 2592 + 6912 + 17280];

#define WQ0 0                  // K1 <8,32>  pitch 8 swz : 6912
#define WQ1 (WQ0 + 6912)       // K2 <32,8>  pitch 20    : 4320
#define WQ2 (WQ1 + 4320)       // K3 <8,8>   pitch 12    : 2592
#define WQ3 (WQ2 + 2592)       // K4 <8,8>
#define WQ4 (WQ3 + 2592)       // K5 <8,32>  pitch 8 swz : 6912
#define WQ5 (WQ4 + 6912)       // K6 <32,32> pitch 20    : 17280

// ---------------------------------------------------------------------------
__global__ void detect_mask(const unsigned int* __restrict__ m) {
    __shared__ int s_u8, s_f32;
    if (threadIdx.x == 0) { s_u8 = 0; s_f32 = 0; }
    __syncthreads();
    int loc_u8 = 0, loc_f32 = 0;
    for (int i = threadIdx.x; i < 65536; i += blockDim.x) {
        unsigned v = m[i];
        if (v == 0x3F800000u) loc_f32 = 1;
        else if (v > 1u)      loc_u8 = 1;
    }
    if (loc_u8)  atomicOr(&s_u8, 1);
    if (loc_f32) atomicOr(&s_f32, 1);
    __syncthreads();
    if (threadIdx.x == 0) g_mtype = s_f32 ? 2 : (s_u8 ? 1 : 0);
}

__global__ void build_compact(const int* __restrict__ nbr,
                              const void* __restrict__ maskv, int N) {
    int n = blockIdx.x * blockDim.x + threadIdx.x;
    if (n >= N) return;
    const int mt = g_mtype;
    const int*           mi = (const int*)maskv;
    const unsigned char* mb = (const unsigned char*)maskv;
    const float*         mf = (const float*)maskv;
    int cnt = 0, first = 0;
    int* lst = &g_l8[(size_t)n * 8];
#pragma unroll 1
    for (int k = 0; k < 27; k++) {
        if (k == 13) continue;
        size_t o = (size_t)k * N + n;
        bool on;
        if (mt == 0)      on = mi[o] != 0;
        else if (mt == 1) on = mb[o] != 0;
        else              on = mf[o] != 0.0f;
        if (on) {
            int e = (k << 20) | nbr[o];
            if (cnt == 0)      first = e;
            else if (cnt < 8)  lst[cnt] = e;
            else               g_lov[(size_t)n * LOV + cnt - 8] = e;
            cnt++;
        }
    }
    lst[0] = first | (cnt << 27);
    if (cnt < 2) lst[1] = 0;
    if (cnt < 3) lst[2] = 0;
    if (cnt < 4) lst[3] = 0;
}

__device__ __forceinline__ unsigned f2b2(float lo, float hi) {
    __nv_bfloat162 p = __floats2bfloat162_rn(lo, hi);
    return *reinterpret_cast<unsigned*>(&p);
}
__device__ __forceinline__ float2 bf2f(unsigned u) {
    float2 r;
    r.x = __uint_as_float(u << 16);
    r.y = __uint_as_float(u & 0xFFFF0000u);
    return r;
}
__device__ __forceinline__ __nv_bfloat162 u2b(unsigned u) {
    return *reinterpret_cast<__nv_bfloat162*>(&u);
}

// Pack one bf16x2 word of W[k][c][oc] -> rows [k][oc][c/2].
// SWZ: add (oc&4) words (chunk swizzle for <8,32> kernels).
// FOLD4: tile fold for Wd0 (source is [27][32][32], sum 4 row-blocks).
template <bool FOLD4, bool SWZ>
__device__ __forceinline__ void pack_one(const float* W, unsigned* dst,
                                         int CIN, int COUT, int PITCH, int i) {
    int c2n = CIN >> 1;
    int c2 = i % c2n;
    int rest = i / c2n;
    int oc = rest % COUT, k = rest / COUT;
    float a, b;
    if constexpr (FOLD4) {
        a = 0.f; b = 0.f;
#pragma unroll
        for (int t = 0; t < 4; t++) {
            a += W[(k * 32 + 2 * c2     + 8 * t) * 32 + oc];
            b += W[(k * 32 + 2 * c2 + 1 + 8 * t) * 32 + oc];
        }
    } else {
        a = W[(k * CIN + 2 * c2) * COUT + oc];
        b = W[(k * CIN + 2 * c2 + 1) * COUT + oc];
    }
    int off = (k * COUT + oc) * PITCH + c2;
    if constexpr (SWZ) off += (oc & 4);
    dst[off] = f2b2(a, b);
}
__global__ void pack_all(const float* __restrict__ Wd0,
                         const float* __restrict__ Wd1,
                         const float* __restrict__ Wd2,
                         const float* __restrict__ Wu0,
                         const float* __restrict__ Wu1,
                         const float* __restrict__ Wu2,
                         unsigned* __restrict__ wp) {
    int i = blockIdx.x * blockDim.x + threadIdx.x;
    const int s0 = 3456, s1 = 3456, s2 = 864, s3 = 864, s4 = 3456, s5 = 13824;
    if (i < s0) { pack_one<true , true >(Wd0, wp + WQ0,  8, 32,  8, i); return; }
    i -= s0;
    if (i < s1) { pack_one<false, false>(Wd1, wp + WQ1, 32,  8, 20, i); return; }
    i -= s1;
    if (i < s2) { pack_one<false, false>(Wd2, wp + WQ2,  8,  8, 12, i); return; }
    i -= s2;
    if (i < s3) { pack_one<false, false>(Wu0, wp + WQ3,  8,  8, 12, i); return; }
    i -= s3;
    if (i < s4) { pack_one<false, true >(Wu1, wp + WQ4,  8, 32,  8, i); return; }
    i -= s4;
    if (i < s5) { pack_one<false, false>(Wu2, wp + WQ5, 32, 32, 20, i); return; }
}

// Pack x [N*8 fp32] -> bf16x2 [N*4]
__global__ void pack_x(const float* __restrict__ x, unsigned* __restrict__ dst,
                       int n4) {
    int i = blockIdx.x * blockDim.x + threadIdx.x;
    if (i >= n4) return;
    float2 v = reinterpret_cast<const float2*>(x)[i];
    dst[i] = f2b2(v.x, v.y);
}

// ---------------------------------------------------------------------------
// Warp-per-voxel (x ILP) sparse conv, packed bf16 HFMA2 inner product.
// EPI: 0 none; 1: out = xres(bf16) - conv (8ch); 2: out = tile(xres fp32)
//      + conv (32ch).
// ---------------------------------------------------------------------------
template <int CIN, int COUT, int EPI, int TB, int MINB, int ILP, bool OUTBF>
__global__ void __launch_bounds__(TB, MINB)
conv_kernel(const unsigned* __restrict__ in,     // bf16x2, CIN/2 words/voxel
            const unsigned* __restrict__ WP,
            const void* __restrict__ xres,
            void* __restrict__ out, int N) {
    constexpr int csn   = (COUT == 32) ? CIN : (CIN / 4);
    constexpr int PITCH = (CIN == 32) ? 20 : ((COUT == 32) ? 8 : 12);
    constexpr bool WSWZ = (CIN == 8) && (COUT == 32);
    extern __shared__ unsigned Ws[];  // [27][COUT][PITCH]

    const int tid = threadIdx.x;
    for (int i = tid; i < 27 * COUT * PITCH; i += blockDim.x)
        Ws[i] = WP[i];
    __syncthreads();

    const int lane = tid & 31;
    const int warp = tid >> 5;
    const int wpb  = blockDim.x >> 5;

    int oc, cs0;
    if (COUT == 32) { oc = lane; cs0 = 0; }
    else            { oc = lane & 7; cs0 = (lane >> 3) * csn; }
    const int wbase = oc * PITCH + (WSWZ ? (oc & 4) : 0) + (cs0 >> 1);

    const int gw      = blockIdx.x * wpb + warp;
    const int gstride = gridDim.x * wpb;

    for (int base = gw * ILP; base < N; base += gstride * ILP) {
        int4 L[ILP];
#pragma unroll
        for (int j = 0; j < ILP; j++) {
            int n = base + j;
            L[j] = (n < N)
                 ? *reinterpret_cast<const int4*>(&g_l8[(size_t)n * 8])
                 : make_int4(0, 0, 0, 0);
        }
#pragma unroll
        for (int j = 0; j < ILP; j++) {
            const int n = base + j;
            if (n >= N) break;
            const int cnt = ((unsigned)L[j].x) >> 27;

            __nv_bfloat162 z = __float2bfloat162_rn(0.f);
            __nv_bfloat162 b0 = z, b1 = z, b2 = z, b3 = z;

            auto do_entry = [&](int e) {
                const int k   = (e >> 20) & 31;
                const int src = e & 0xFFFFF;
                const unsigned* gp = in + (size_t)src * (CIN / 2) + (cs0 >> 1);
                const unsigned* wrow = &Ws[k * (COUT * PITCH) + wbase];
                if constexpr (csn == 2) {
                    b0 = __hfma2(u2b(gp[0]), u2b(wrow[0]), b0);
                } else {
#pragma unroll
                    for (int b = 0; b < csn / 8; b++) {
                        uint4 gv = reinterpret_cast<const uint4*>(gp)[b];
                        uint4 wv = reinterpret_cast<const uint4*>(wrow)[b];
                        b0 = __hfma2(u2b(gv.x), u2b(wv.x), b0);
                        b1 = __hfma2(u2b(gv.y), u2b(wv.y), b1);
                        b2 = __hfma2(u2b(gv.z), u2b(wv.z), b2);
                        b3 = __hfma2(u2b(gv.w), u2b(wv.w), b3);
                    }
                }
            };

            do_entry((13 << 20) | n);                 // center tap
            if (cnt > 0) do_entry(L[j].x & 0x07FFFFFF);
            if (cnt > 1) do_entry(L[j].y);
            if (cnt > 2) do_entry(L[j].z);
            if (cnt > 3) do_entry(L[j].w);
            if (cnt > 4) {
                int4 M = *reinterpret_cast<const int4*>(&g_l8[(size_t)n * 8 + 4]);
                do_entry(M.x);
                if (cnt > 5) do_entry(M.y);
                if (cnt > 6) do_entry(M.z);
                if (cnt > 7) do_entry(M.w);
#pragma unroll 1
                for (int i = 8; i < cnt; i++)
                    do_entry(g_lov[(size_t)n * LOV + i - 8]);
            }

            float2 f0 = bf2f(*reinterpret_cast<unsigned*>(&b0));
            float2 f1 = bf2f(*reinterpret_cast<unsigned*>(&b1));
            float2 f2 = bf2f(*reinterpret_cast<unsigned*>(&b2));
            float2 f3 = bf2f(*reinterpret_cast<unsigned*>(&b3));
            float acc = ((f0.x + f0.y) + (f1.x + f1.y))
                      + ((f2.x + f2.y) + (f3.x + f3.y));

            if constexpr (COUT == 8) {
                acc += __shfl_xor_sync(0xffffffffu, acc, 8);
                acc += __shfl_xor_sync(0xffffffffu, acc, 16);
                float v = acc;
                if constexpr (EPI == 1) {
                    unsigned xp = ((const unsigned*)xres)
                                      [(size_t)n * 4 + ((lane & 7) >> 1)];
                    float2 xv = bf2f(xp);
                    v = ((lane & 1) ? xv.y : xv.x) - v;
                }
                if constexpr (OUTBF) {
                    float pv = __shfl_xor_sync(0xffffffffu, v, 1);
                    if (lane < 8 && (lane & 1) == 0)
                        ((unsigned*)out)[(size_t)n * 4 + (lane >> 1)] = f2b2(v, pv);
                } else {
                    if (lane < 8)
                        ((float*)out)[(size_t)n * 8 + lane] = v;
                }
            } else {
                float v = acc;
                if constexpr (EPI == 2)
                    v += ((const float*)xres)[(size_t)n * 8 + (lane & 7)];
                if constexpr (OUTBF) {
                    float pv = __shfl_xor_sync(0xffffffffu, v, 1);
                    if ((lane & 1) == 0)
                        ((unsigned*)out)[(size_t)n * 16 + (lane >> 1)] = f2b2(v, pv);
                } else {
                    ((float*)out)[(size_t)n * 32 + lane] = v;
                }
            }
        }
    }
}

// ---------------------------------------------------------------------------
extern "C" void kernel_launch(void* const* d_in, const int* in_sizes, int n_in,
                              void* d_out, int out_size) {
    const float* x    = (const float*)d_in[0];
    const int*   nbr  = (const int*)d_in[1];
    const void*  mask = (const void*)d_in[2];
    const float* Wd0  = (const float*)d_in[3];
    const float* Wd1  = (const float*)d_in[4];
    const float* Wd2  = (const float*)d_in[5];
    const float* Wu0  = (const float*)d_in[6];
    const float* Wu1  = (const float*)d_in[7];
    const float* Wu2  = (const float*)d_in[8];
    float*       out  = (float*)d_out;
    const int N = in_sizes[0] / 8;

    unsigned *xbf, *t32, *t8a, *t8b, *wp;
    cudaGetSymbolAddress((void**)&xbf, g_xbf);
    cudaGetSymbolAddress((void**)&t32, g_t32p);
    cudaGetSymbolAddress((void**)&t8a, g_t8ap);
    cudaGetSymbolAddress((void**)&t8b, g_t8bp);
    cudaGetSymbolAddress((void**)&wp,  g_wpack);

    const int sm_8_32  = 6912  * 4;   // 27,648 B
    const int sm_32_8  = 4320  * 4;   // 17,280 B
    const int sm_8_8   = 2592  * 4;   // 10,368 B
    const int sm_32_32 = 17280 * 4;   // 69,120 B

    cudaFuncSetAttribute(
        (const void*)conv_kernel<32, 32, 2, 512, 2, 2, false>,
        cudaFuncAttributeMaxDynamicSharedMemorySize, sm_32_32);

    detect_mask<<<1, 1024>>>((const unsigned int*)mask);
    build_compact<<<(N + 511) / 512, 512>>>(nbr, mask, N);
    pack_x<<<(N * 4 + 255) / 256, 256>>>(x, xbf, N * 4);
    pack_all<<<(3456 * 3 + 864 * 2 + 13824 + 255) / 256, 256>>>(
        Wd0, Wd1, Wd2, Wu0, Wu1, Wu2, wp);

    // K1: 8 -> 32 (tile folded into packed weights)
    conv_kernel<8, 32, 0, 256, 6, 2, true>
        <<<NSM * 6, 256, sm_8_32>>>(xbf, wp + WQ0, x, t32, N);
    // K2: 32 -> 8
    conv_kernel<32, 8, 0, 256, 6, 2, true>
        <<<NSM * 6, 256, sm_32_8>>>(t32, wp + WQ1, x, t8a, N);
    // K3: 8 -> 8, epilogue r = x(bf16) - d
    conv_kernel<8, 8, 1, 256, 6, 4, true>
        <<<NSM * 6, 256, sm_8_8>>>(t8a, wp + WQ2, xbf, t8b, N);
    // K4: 8 -> 8
    conv_kernel<8, 8, 0, 256, 6, 4, true>
        <<<NSM * 6, 256, sm_8_8>>>(t8b, wp + WQ3, x, t8a, N);
    // K5: 8 -> 32
    conv_kernel<8, 32, 0, 256, 6, 2, true>
        <<<NSM * 6, 256, sm_8_32>>>(t8a, wp + WQ4, x, t32, N);
    // K6: 32 -> 32, epilogue out = tile(x fp32) + conv
    conv_kernel<32, 32, 2, 512, 2, 2, false>
        <<<NSM * 2, 512, sm_32_32>>>(t32, wp + WQ5, x, out, N);
}